// round 3
// baseline (speedup 1.0000x reference)
#include <cuda_runtime.h>
#include <cuda_bf16.h>
#include <math.h>

#define BB 4
#define CC 256
#define CQ 32
#define NN 3136

// ---------------- scratch (device globals: allocation-free) ----------------
__device__ float g_q[(size_t)BB * NN * CQ];        // q transposed [B][N][32]
__device__ float g_k[(size_t)BB * NN * CQ];        // k transposed [B][N][32]
__device__ float g_v[(size_t)BB * CC * NN];        // v [B][C][N]
__device__ float g_att[(size_t)BB * NN * NN];      // energy -> attention [B][N][N]
__device__ float g_scalars[4];                     // [0] = 1/norm_value

// buffer selector for the generic GEMM (resolved device-side, so host code
// needs no cudaGetSymbolAddress — kernel_launch stays pure kernel-launches)
#define BUF_EXT 0
#define BUF_Q   1
#define BUF_K   2
#define BUF_V   3
#define BUF_ATT 4

__device__ __forceinline__ float* resolve_buf(int sel, float* ext) {
    switch (sel) {
        case BUF_Q:   return g_q;
        case BUF_K:   return g_k;
        case BUF_V:   return g_v;
        case BUF_ATT: return g_att;
        default:      return ext;
    }
}

// ---------------- reductions ----------------
__device__ __forceinline__ float warpRedMax(float v) {
#pragma unroll
    for (int o = 16; o > 0; o >>= 1) v = fmaxf(v, __shfl_xor_sync(0xffffffffu, v, o));
    return v;
}
__device__ __forceinline__ float warpRedSum(float v) {
#pragma unroll
    for (int o = 16; o > 0; o >>= 1) v += __shfl_xor_sync(0xffffffffu, v, o);
    return v;
}

// ---------------- norm_value from weights ----------------
__global__ void norm_kernel(const float* __restrict__ Wq,
                            const float* __restrict__ Wk,
                            const float* __restrict__ Wv) {
    __shared__ float ssum[8];
    __shared__ float smax[8];
    int tid = threadIdx.x, lane = tid & 31, wid = tid >> 5;

    // u^2 = ||Wq||_F^2  (32*256 elements)
    float s = 0.f;
    for (int i = tid; i < CQ * CC; i += 256) { float w = Wq[i]; s = fmaf(w, w, s); }

    // column norms: vn_c over 32 rows of Wk, wn_c over 256 rows of Wv (c = tid)
    float vk = 0.f;
#pragma unroll
    for (int o = 0; o < CQ; o++) { float w = Wk[o * CC + tid]; vk = fmaf(w, w, vk); }
    float vv = 0.f;
    for (int o = 0; o < CC; o++) { float w = Wv[o * CC + tid]; vv = fmaf(w, w, vv); }
    float m = fmaxf(vk, vv);

    s = warpRedSum(s);
    m = warpRedMax(m);
    if (lane == 0) { ssum[wid] = s; smax[wid] = m; }
    __syncthreads();
    if (tid == 0) {
        float u2 = 0.f, mm = -1e30f;
#pragma unroll
        for (int i = 0; i < 8; i++) { u2 += ssum[i]; mm = fmaxf(mm, smax[i]); }
        g_scalars[0] = 1.0f / (sqrtf(u2) * sqrtf(mm));   // 1 / (u * max(vn, wn))
    }
}

// ---------------- q,k projection (outputs transposed [B][N][32]) ----------------
__global__ __launch_bounds__(256) void qk_proj(const float* __restrict__ x,
                                               const float* __restrict__ Wq,
                                               const float* __restrict__ bq,
                                               const float* __restrict__ Wk,
                                               const float* __restrict__ bk) {
    __shared__ float Wqs[CQ][128];
    __shared__ float Wks[CQ][128];
    const int tid = threadIdx.x;
    const int b = blockIdx.y;
    const int n = blockIdx.x * 256 + tid;

    float accq[CQ], acck[CQ];
#pragma unroll
    for (int o = 0; o < CQ; o++) { accq[o] = bq[o]; acck[o] = bk[o]; }

    const float* xb = x + (size_t)b * CC * NN;

    for (int cc = 0; cc < CC; cc += 128) {
        for (int t = tid; t < CQ * 128; t += 256) {
            int o = t >> 7, c = t & 127;
            Wqs[o][c] = Wq[o * CC + cc + c];
            Wks[o][c] = Wk[o * CC + cc + c];
        }
        __syncthreads();
        if (n < NN) {
            for (int ci = 0; ci < 128; ci++) {
                float xv = xb[(size_t)(cc + ci) * NN + n];
#pragma unroll
                for (int o = 0; o < CQ; o++) {
                    accq[o] = fmaf(Wqs[o][ci], xv, accq[o]);
                    acck[o] = fmaf(Wks[o][ci], xv, acck[o]);
                }
            }
        }
        __syncthreads();
    }
    if (n < NN) {
        float4* qp = (float4*)(g_q + ((size_t)b * NN + n) * CQ);
        float4* kp = (float4*)(g_k + ((size_t)b * NN + n) * CQ);
#pragma unroll
        for (int u = 0; u < 8; u++) {
            qp[u] = make_float4(accq[4 * u], accq[4 * u + 1], accq[4 * u + 2], accq[4 * u + 3]);
            kp[u] = make_float4(acck[4 * u], acck[4 * u + 1], acck[4 * u + 2], acck[4 * u + 3]);
        }
    }
}

// ---------------- generic tiled fp32 GEMM ----------------
// C[m][n] = sum_k A[m][k] * B'[k][n]
//   A row-major [M][K] (K-contiguous)
//   TRANS_B=false: B given as [K][Nn] (n-contiguous)
//   TRANS_B=true : B given as Bt[Nn][K] (k-contiguous)
// MODE 0: += bias[m] (aux = bias, sAux = 0)
// MODE 1: C = (gamma[0]*scale)*acc + aux[bz*sAux + m*Nn+n]  (epilogue, aux = x)
// MODE 2: C = acc * g_scalars[0]                            (energy scaling)
template <bool TRANS_B, int MODE>
__global__ __launch_bounds__(256) void gemm_kernel(const float* __restrict__ Aext,
                                                   const float* __restrict__ Bext,
                                                   float* __restrict__ Cext,
                                                   const float* __restrict__ aux,
                                                   const float* __restrict__ gamma,
                                                   int selA, int selB, int selC,
                                                   int M, int Nn, int K,
                                                   long sA, long sB, long sC, long sAux,
                                                   float scale) {
    __shared__ float As[32][132];
    __shared__ float Bs[32][132];
    const int tid = threadIdx.x;
    const int bz = blockIdx.z;
    const int m0 = blockIdx.y * 128;
    const int n0 = blockIdx.x * 128;

    const float* A = resolve_buf(selA, (float*)Aext) + (long)bz * sA;
    const float* Bm = resolve_buf(selB, (float*)Bext) + (long)bz * sB;
    float* C = resolve_buf(selC, Cext) + (long)bz * sC;
    if (aux) aux += (long)bz * sAux;    // batch offset for residual/bias source

    float acc[8][8];
#pragma unroll
    for (int i = 0; i < 8; i++)
#pragma unroll
        for (int j = 0; j < 8; j++) acc[i][j] = 0.f;

    const int tm = (tid & 15) * 4;
    const int tn = (tid >> 4) * 4;
    const int tr = tid >> 3;   // 0..31 row within transpose-load pass
    const int tk4 = tid & 7;   // k-quad within transpose-load
    const int dk = tid >> 5;   // 0..7 for direct B load
    const int dn4 = tid & 31;  // n-quad for direct B load

    for (int k0 = 0; k0 < K; k0 += 32) {
        // A: transpose on load -> As[k][m]
#pragma unroll
        for (int p = 0; p < 4; p++) {
            int m = tr + p * 32;
            int row = m0 + m;
            float4 av = make_float4(0.f, 0.f, 0.f, 0.f);
            if (row < M) av = *(const float4*)(A + (long)row * K + k0 + tk4 * 4);
            As[tk4 * 4 + 0][m] = av.x;
            As[tk4 * 4 + 1][m] = av.y;
            As[tk4 * 4 + 2][m] = av.z;
            As[tk4 * 4 + 3][m] = av.w;
        }
        if (TRANS_B) {
#pragma unroll
            for (int p = 0; p < 4; p++) {
                int nb = tr + p * 32;
                int row = n0 + nb;
                float4 bv = make_float4(0.f, 0.f, 0.f, 0.f);
                if (row < Nn) bv = *(const float4*)(Bm + (long)row * K + k0 + tk4 * 4);
                Bs[tk4 * 4 + 0][nb] = bv.x;
                Bs[tk4 * 4 + 1][nb] = bv.y;
                Bs[tk4 * 4 + 2][nb] = bv.z;
                Bs[tk4 * 4 + 3][nb] = bv.w;
            }
        } else {
#pragma unroll
            for (int p = 0; p < 4; p++) {
                int k = dk + p * 8;
                int col = n0 + dn4 * 4;
                float4 bv = make_float4(0.f, 0.f, 0.f, 0.f);
                if (col < Nn) bv = *(const float4*)(Bm + (long)(k0 + k) * Nn + col);
                *(float4*)&Bs[k][dn4 * 4] = bv;
            }
        }
        __syncthreads();
#pragma unroll
        for (int k = 0; k < 32; k++) {
            float ar[8], br[8];
            *(float4*)&ar[0] = *(const float4*)&As[k][tm];
            *(float4*)&ar[4] = *(const float4*)&As[k][tm + 64];
            *(float4*)&br[0] = *(const float4*)&Bs[k][tn];
            *(float4*)&br[4] = *(const float4*)&Bs[k][tn + 64];
#pragma unroll
            for (int i = 0; i < 8; i++)
#pragma unroll
                for (int j = 0; j < 8; j++) acc[i][j] = fmaf(ar[i], br[j], acc[i][j]);
        }
        __syncthreads();
    }

    float gam = 0.f, snorm = 0.f;
    if (MODE == 1) gam = gamma[0] * scale;
    if (MODE == 2) snorm = g_scalars[0];

#pragma unroll
    for (int i = 0; i < 8; i++) {
        int mi = m0 + tm + ((i < 4) ? i : 60 + i);
        if (mi >= M) continue;
#pragma unroll
        for (int j = 0; j < 8; j++) {
            int nj = n0 + tn + ((j < 4) ? j : 60 + j);
            if (nj >= Nn) continue;
            float v = acc[i][j];
            if (MODE == 0) v += aux[mi];
            else if (MODE == 1) v = fmaf(gam, v, aux[(long)mi * Nn + nj]);
            else v *= snorm;
            C[(long)mi * Nn + nj] = v;
        }
    }
}

// ---------------- row softmax in-place over g_att ----------------
__global__ __launch_bounds__(256) void softmax_rows() {
    __shared__ float e[NN];
    __shared__ float red[8];
    const int tid = threadIdx.x, lane = tid & 31, wid = tid >> 5;
    float* a = g_att + (size_t)blockIdx.x * NN;

    float lmax = -1e30f;
    for (int j = tid; j < NN; j += 256) {
        float v = a[j];
        e[j] = v;
        lmax = fmaxf(lmax, v);
    }
    lmax = warpRedMax(lmax);
    if (lane == 0) red[wid] = lmax;
    __syncthreads();
    float rmax = red[0];
#pragma unroll
    for (int i = 1; i < 8; i++) rmax = fmaxf(rmax, red[i]);
    __syncthreads();

    float lsum = 0.f;
    for (int j = tid; j < NN; j += 256) {
        float p = __expf(e[j] - rmax);
        e[j] = p;
        lsum += p;
    }
    lsum = warpRedSum(lsum);
    if (lane == 0) red[wid] = lsum;
    __syncthreads();
    float rsum = red[0];
#pragma unroll
    for (int i = 1; i < 8; i++) rsum += red[i];
    float inv = 1.0f / rsum;
    for (int j = tid; j < NN; j += 256) a[j] = e[j] * inv;
}

// ---------------- launch ----------------
extern "C" void kernel_launch(void* const* d_in, const int* in_sizes, int n_in,
                              void* d_out, int out_size) {
    const float* x = (const float*)d_in[0];
    const float* Wq = (const float*)d_in[1];
    const float* bq = (const float*)d_in[2];
    const float* Wk = (const float*)d_in[3];
    const float* bk = (const float*)d_in[4];
    const float* Wv = (const float*)d_in[5];
    const float* bv = (const float*)d_in[6];
    const float* gamma = (const float*)d_in[7];
    float* out = (float*)d_out;

    // 1) norm_value
    norm_kernel<<<1, 256>>>(Wq, Wk, Wv);

    // 2) q, k projections (transposed outputs into g_q/g_k)
    qk_proj<<<dim3((NN + 255) / 256, BB), 256>>>(x, Wq, bq, Wk, bk);

    // 3) v = Wv x + bv : M=256, N=3136, K=256  (A=Wv ext, B=x ext, C=g_v)
    gemm_kernel<false, 0><<<dim3((NN + 127) / 128, CC / 128, BB), 256>>>(
        Wv, x, nullptr, bv, nullptr,
        BUF_EXT, BUF_EXT, BUF_V,
        CC, NN, CC,
        0L, (long)CC * NN, (long)CC * NN, 0L, 0.f);

    // 4) energy = (qT kT^T) / norm : M=N=3136, K=32  (A=g_q, B=g_k, C=g_att)
    gemm_kernel<true, 2><<<dim3((NN + 127) / 128, (NN + 127) / 128, BB), 256>>>(
        nullptr, nullptr, nullptr, nullptr, nullptr,
        BUF_Q, BUF_K, BUF_ATT,
        NN, NN, CQ,
        (long)NN * CQ, (long)NN * CQ, (long)NN * NN, 0L, 0.f);

    // 5) softmax over rows of g_att
    softmax_rows<<<BB * NN, 256>>>();

    // 6) out = gamma * (v attn^T) / bound + x : M=256, N=3136, K=3136
    //    aux = x WITH batch stride (this was the round-2 bug: rel_err=sqrt(1.5))
    double bound = exp(sqrt(3.0)) * sqrt((double)NN / (double)CC) + 2.0 * sqrt(6.0);
    float inv_bound = (float)(1.0 / bound);
    gemm_kernel<true, 1><<<dim3((NN + 127) / 128, CC / 128, BB), 256>>>(
        nullptr, nullptr, out, x, gamma,
        BUF_V, BUF_ATT, BUF_EXT,
        CC, NN, NN,
        (long)CC * NN, (long)NN * NN, (long)CC * NN, (long)CC * NN, inv_bound);
}

// round 4
// speedup vs baseline: 2.9107x; 2.9107x over previous
#include <cuda_runtime.h>
#include <cuda_bf16.h>
#include <math.h>
#include <stdint.h>

#define BB 4
#define CC 256
#define CQ 32
#define NN 3136

// ---------------- scratch (device globals: allocation-free) ----------------
__device__ __nv_bfloat16 g_qh[(size_t)BB * NN * CQ];     // q [B][N][32] bf16
__device__ __nv_bfloat16 g_kh[(size_t)BB * NN * CQ];     // k [B][N][32] bf16
__device__ __nv_bfloat16 g_vh[(size_t)BB * CC * NN];     // v [B][C][N] bf16
__device__ __nv_bfloat16 g_att[(size_t)BB * NN * NN];    // energy->attn [B][N][N] bf16
__device__ float g_scalars[4];                           // [0] = 1/norm_value

// ---------------- reductions ----------------
__device__ __forceinline__ float warpRedMax(float v) {
#pragma unroll
    for (int o = 16; o > 0; o >>= 1) v = fmaxf(v, __shfl_xor_sync(0xffffffffu, v, o));
    return v;
}
__device__ __forceinline__ float warpRedSum(float v) {
#pragma unroll
    for (int o = 16; o > 0; o >>= 1) v += __shfl_xor_sync(0xffffffffu, v, o);
    return v;
}

// ---------------- norm_value from weights ----------------
__global__ void norm_kernel(const float* __restrict__ Wq,
                            const float* __restrict__ Wk,
                            const float* __restrict__ Wv) {
    __shared__ float ssum[8];
    __shared__ float smax[8];
    int tid = threadIdx.x, lane = tid & 31, wid = tid >> 5;

    float s = 0.f;
    for (int i = tid; i < CQ * CC; i += 256) { float w = Wq[i]; s = fmaf(w, w, s); }

    float vk = 0.f;
#pragma unroll
    for (int o = 0; o < CQ; o++) { float w = Wk[o * CC + tid]; vk = fmaf(w, w, vk); }
    float vv = 0.f;
    for (int o = 0; o < CC; o++) { float w = Wv[o * CC + tid]; vv = fmaf(w, w, vv); }
    float m = fmaxf(vk, vv);

    s = warpRedSum(s);
    m = warpRedMax(m);
    if (lane == 0) { ssum[wid] = s; smax[wid] = m; }
    __syncthreads();
    if (tid == 0) {
        float u2 = 0.f, mm = -1e30f;
#pragma unroll
        for (int i = 0; i < 8; i++) { u2 += ssum[i]; mm = fmaxf(mm, smax[i]); }
        g_scalars[0] = 1.0f / (sqrtf(u2) * sqrtf(mm));
    }
}

// ---------------- q,k projection -> bf16 transposed [B][N][32] ----------------
__global__ __launch_bounds__(256) void qk_proj(const float* __restrict__ x,
                                               const float* __restrict__ Wq,
                                               const float* __restrict__ bq,
                                               const float* __restrict__ Wk,
                                               const float* __restrict__ bk) {
    __shared__ float Wqs[CQ][128];
    __shared__ float Wks[CQ][128];
    const int tid = threadIdx.x;
    const int b = blockIdx.y;
    const int n = blockIdx.x * 256 + tid;

    float accq[CQ], acck[CQ];
#pragma unroll
    for (int o = 0; o < CQ; o++) { accq[o] = bq[o]; acck[o] = bk[o]; }

    const float* xb = x + (size_t)b * CC * NN;

    for (int cc = 0; cc < CC; cc += 128) {
        for (int t = tid; t < CQ * 128; t += 256) {
            int o = t >> 7, c = t & 127;
            Wqs[o][c] = Wq[o * CC + cc + c];
            Wks[o][c] = Wk[o * CC + cc + c];
        }
        __syncthreads();
        if (n < NN) {
            for (int ci = 0; ci < 128; ci++) {
                float xv = xb[(size_t)(cc + ci) * NN + n];
#pragma unroll
                for (int o = 0; o < CQ; o++) {
                    accq[o] = fmaf(Wqs[o][ci], xv, accq[o]);
                    acck[o] = fmaf(Wks[o][ci], xv, acck[o]);
                }
            }
        }
        __syncthreads();
    }
    if (n < NN) {
        __nv_bfloat16 hq[CQ], hk[CQ];
#pragma unroll
        for (int o = 0; o < CQ; o++) {
            hq[o] = __float2bfloat16(accq[o]);
            hk[o] = __float2bfloat16(acck[o]);
        }
        uint4* qp = (uint4*)(g_qh + ((size_t)b * NN + n) * CQ);
        uint4* kp = (uint4*)(g_kh + ((size_t)b * NN + n) * CQ);
#pragma unroll
        for (int u = 0; u < 4; u++) {
            qp[u] = ((const uint4*)hq)[u];
            kp[u] = ((const uint4*)hk)[u];
        }
    }
}

// ---------------- v = Wv x + bv (fp32 SIMT), output bf16 [B][C][N] ----------------
__global__ __launch_bounds__(256) void v_gemm(const float* __restrict__ Wv,
                                              const float* __restrict__ x,
                                              const float* __restrict__ bv) {
    __shared__ float As[32][132];
    __shared__ float Bs[32][132];
    const int tid = threadIdx.x;
    const int bz = blockIdx.z;
    const int m0 = blockIdx.y * 128;
    const int n0 = blockIdx.x * 128;

    const float* A = Wv;                       // [256][256]
    const float* Bm = x + (size_t)bz * CC * NN; // [256][3136]
    __nv_bfloat16* C = g_vh + (size_t)bz * CC * NN;

    float acc[8][8];
#pragma unroll
    for (int i = 0; i < 8; i++)
#pragma unroll
        for (int j = 0; j < 8; j++) acc[i][j] = 0.f;

    const int tm = (tid & 15) * 4;
    const int tn = (tid >> 4) * 4;
    const int tr = tid >> 3;
    const int tk4 = tid & 7;
    const int dk = tid >> 5;
    const int dn4 = tid & 31;

    for (int k0 = 0; k0 < CC; k0 += 32) {
#pragma unroll
        for (int p = 0; p < 4; p++) {
            int m = tr + p * 32;
            int row = m0 + m;
            float4 av = make_float4(0.f, 0.f, 0.f, 0.f);
            if (row < CC) av = *(const float4*)(A + (long)row * CC + k0 + tk4 * 4);
            As[tk4 * 4 + 0][m] = av.x;
            As[tk4 * 4 + 1][m] = av.y;
            As[tk4 * 4 + 2][m] = av.z;
            As[tk4 * 4 + 3][m] = av.w;
        }
#pragma unroll
        for (int p = 0; p < 4; p++) {
            int k = dk + p * 8;
            int col = n0 + dn4 * 4;
            float4 bvv = make_float4(0.f, 0.f, 0.f, 0.f);
            if (col < NN) bvv = *(const float4*)(Bm + (long)(k0 + k) * NN + col);
            *(float4*)&Bs[k][dn4 * 4] = bvv;
        }
        __syncthreads();
#pragma unroll
        for (int k = 0; k < 32; k++) {
            float ar[8], br[8];
            *(float4*)&ar[0] = *(const float4*)&As[k][tm];
            *(float4*)&ar[4] = *(const float4*)&As[k][tm + 64];
            *(float4*)&br[0] = *(const float4*)&Bs[k][tn];
            *(float4*)&br[4] = *(const float4*)&Bs[k][tn + 64];
#pragma unroll
            for (int i = 0; i < 8; i++)
#pragma unroll
                for (int j = 0; j < 8; j++) acc[i][j] = fmaf(ar[i], br[j], acc[i][j]);
        }
        __syncthreads();
    }

#pragma unroll
    for (int i = 0; i < 8; i++) {
        int mi = m0 + tm + ((i < 4) ? i : 60 + i);
        if (mi >= CC) continue;
        float bias = bv[mi];
#pragma unroll
        for (int j = 0; j < 8; j++) {
            int nj = n0 + tn + ((j < 4) ? j : 60 + j);
            if (nj >= NN) continue;
            C[(long)mi * NN + nj] = __float2bfloat16(acc[i][j] + bias);
        }
    }
}

// ---------------- tensor-core bf16 GEMM: C = A[M][K] * B[N][K]^T ----------------
// MODE 2: energy = (q k^T) * g_scalars[0]  -> bf16 g_att   (M=N=NN, K=32)
// MODE 1: out = gamma*inv_bound*(v att^T) + x -> fp32 d_out (M=CC, N=NN, K=NN)
template <int MODE>
__global__ __launch_bounds__(256) void tc_gemm(float* __restrict__ outp,
                                               const float* __restrict__ xres,
                                               const float* __restrict__ gamma,
                                               float inv_bound) {
    constexpr int M = (MODE == 2) ? NN : CC;
    constexpr int K_ = (MODE == 2) ? CQ : NN;
    constexpr int KT = (MODE == 2) ? 32 : 64;
    constexpr int PITCH = KT + 8;

    __shared__ __nv_bfloat16 As[128 * PITCH];
    __shared__ __nv_bfloat16 Bs[128 * PITCH];

    const int tid = threadIdx.x;
    const int lane = tid & 31;
    const int wid = tid >> 5;
    const int wm = (wid >> 2) * 64;   // warp m offset (2 warps in m)
    const int wn = (wid & 3) * 32;    // warp n offset (4 warps in n)
    const int bz = blockIdx.z;
    const int m0 = blockIdx.y * 128;
    const int n0 = blockIdx.x * 128;

    const __nv_bfloat16* A =
        (MODE == 2) ? (g_qh + (size_t)bz * NN * CQ) : (g_vh + (size_t)bz * CC * NN);
    const __nv_bfloat16* B =
        (MODE == 2) ? (g_kh + (size_t)bz * NN * CQ) : (g_att + (size_t)bz * NN * NN);

    float acc[4][4][4];
#pragma unroll
    for (int a = 0; a < 4; a++)
#pragma unroll
        for (int b = 0; b < 4; b++)
#pragma unroll
            for (int c = 0; c < 4; c++) acc[a][b][c] = 0.f;

    constexpr int TPR = KT / 8;     // threads per row (8 bf16 = 16B each)
    constexpr int RPP = 256 / TPR;  // rows per pass
    constexpr int NP = 128 / RPP;   // passes
    const int lk = (tid % TPR) * 8;
    const int lrow = tid / TPR;

    for (int k0 = 0; k0 < K_; k0 += KT) {
#pragma unroll
        for (int p = 0; p < NP; p++) {
            int r = lrow + p * RPP;
            int grow = m0 + r;
            uint4 v = make_uint4(0u, 0u, 0u, 0u);
            if (grow < M) v = *(const uint4*)(A + (size_t)grow * K_ + k0 + lk);
            *(uint4*)&As[r * PITCH + lk] = v;
        }
#pragma unroll
        for (int p = 0; p < NP; p++) {
            int r = lrow + p * RPP;
            int grow = n0 + r;
            uint4 v = make_uint4(0u, 0u, 0u, 0u);
            if (grow < NN) v = *(const uint4*)(B + (size_t)grow * K_ + k0 + lk);
            *(uint4*)&Bs[r * PITCH + lk] = v;
        }
        __syncthreads();

#pragma unroll
        for (int kk = 0; kk < KT / 16; kk++) {
            const int kb = kk * 16;
            uint32_t af[4][4], bf[4][2];
#pragma unroll
            for (int mi = 0; mi < 4; mi++) {
                const __nv_bfloat16* p0 =
                    &As[(wm + mi * 16 + (lane >> 2)) * PITCH + kb + (lane & 3) * 2];
                af[mi][0] = *(const uint32_t*)p0;
                af[mi][1] = *(const uint32_t*)(p0 + 8 * PITCH);
                af[mi][2] = *(const uint32_t*)(p0 + 8);
                af[mi][3] = *(const uint32_t*)(p0 + 8 * PITCH + 8);
            }
#pragma unroll
            for (int ni = 0; ni < 4; ni++) {
                const __nv_bfloat16* p0 =
                    &Bs[(wn + ni * 8 + (lane >> 2)) * PITCH + kb + (lane & 3) * 2];
                bf[ni][0] = *(const uint32_t*)p0;
                bf[ni][1] = *(const uint32_t*)(p0 + 8);
            }
#pragma unroll
            for (int mi = 0; mi < 4; mi++)
#pragma unroll
                for (int ni = 0; ni < 4; ni++) {
                    asm volatile(
                        "mma.sync.aligned.m16n8k16.row.col.f32.bf16.bf16.f32 "
                        "{%0,%1,%2,%3}, {%4,%5,%6,%7}, {%8,%9}, {%0,%1,%2,%3};\n"
                        : "+f"(acc[mi][ni][0]), "+f"(acc[mi][ni][1]),
                          "+f"(acc[mi][ni][2]), "+f"(acc[mi][ni][3])
                        : "r"(af[mi][0]), "r"(af[mi][1]), "r"(af[mi][2]), "r"(af[mi][3]),
                          "r"(bf[ni][0]), "r"(bf[ni][1]));
                }
        }
        __syncthreads();
    }

    // ---------- epilogue ----------
    if (MODE == 2) {
        const float s = g_scalars[0];
        __nv_bfloat16* C = g_att + (size_t)bz * NN * NN;
#pragma unroll
        for (int mi = 0; mi < 4; mi++)
#pragma unroll
            for (int ni = 0; ni < 4; ni++) {
                int row = m0 + wm + mi * 16 + (lane >> 2);
                int col = n0 + wn + ni * 8 + (lane & 3) * 2;
                if (col < NN) {
                    if (row < NN) {
                        __nv_bfloat162 pr =
                            __floats2bfloat162_rn(acc[mi][ni][0] * s, acc[mi][ni][1] * s);
                        *(__nv_bfloat162*)(C + (size_t)row * NN + col) = pr;
                    }
                    if (row + 8 < NN) {
                        __nv_bfloat162 pr =
                            __floats2bfloat162_rn(acc[mi][ni][2] * s, acc[mi][ni][3] * s);
                        *(__nv_bfloat162*)(C + (size_t)(row + 8) * NN + col) = pr;
                    }
                }
            }
    } else {
        const float gam = gamma[0] * inv_bound;
        float* C = outp + (size_t)bz * CC * NN;
        const float* xr = xres + (size_t)bz * CC * NN;
#pragma unroll
        for (int mi = 0; mi < 4; mi++)
#pragma unroll
            for (int ni = 0; ni < 4; ni++) {
                int row = m0 + wm + mi * 16 + (lane >> 2);
                int col = n0 + wn + ni * 8 + (lane & 3) * 2;
                if (col < NN) {
                    {
                        size_t off = (size_t)row * NN + col;
                        float2 r;
                        r.x = fmaf(gam, acc[mi][ni][0], xr[off]);
                        r.y = fmaf(gam, acc[mi][ni][1], xr[off + 1]);
                        *(float2*)(C + off) = r;
                    }
                    {
                        size_t off = (size_t)(row + 8) * NN + col;
                        float2 r;
                        r.x = fmaf(gam, acc[mi][ni][2], xr[off]);
                        r.y = fmaf(gam, acc[mi][ni][3], xr[off + 1]);
                        *(float2*)(C + off) = r;
                    }
                }
            }
    }
}

// ---------------- row softmax in-place over bf16 g_att ----------------
__global__ __launch_bounds__(256) void softmax_rows() {
    constexpr int NC = NN / 8;  // 392 chunks of 8 bf16
    __shared__ float e[NN];
    __shared__ float red[8];
    const int tid = threadIdx.x, lane = tid & 31, wid = tid >> 5;
    __nv_bfloat16* a = g_att + (size_t)blockIdx.x * NN;

    float lmax = -1e30f;
    for (int c = tid; c < NC; c += 256) {
        uint4 u = *(const uint4*)(a + c * 8);
        const __nv_bfloat16* h = (const __nv_bfloat16*)&u;
#pragma unroll
        for (int i = 0; i < 8; i++) {
            float v = __bfloat162float(h[i]);
            e[c * 8 + i] = v;
            lmax = fmaxf(lmax, v);
        }
    }
    lmax = warpRedMax(lmax);
    if (lane == 0) red[wid] = lmax;
    __syncthreads();
    float rmax = red[0];
#pragma unroll
    for (int i = 1; i < 8; i++) rmax = fmaxf(rmax, red[i]);
    __syncthreads();

    float lsum = 0.f;
    for (int j = tid; j < NN; j += 256) {
        float p = __expf(e[j] - rmax);
        e[j] = p;
        lsum += p;
    }
    lsum = warpRedSum(lsum);
    if (lane == 0) red[wid] = lsum;
    __syncthreads();
    float rsum = red[0];
#pragma unroll
    for (int i = 1; i < 8; i++) rsum += red[i];
    float inv = 1.0f / rsum;

    for (int c = tid; c < NC; c += 256) {
        __nv_bfloat16 h[8];
#pragma unroll
        for (int i = 0; i < 8; i++) h[i] = __float2bfloat16(e[c * 8 + i] * inv);
        *(uint4*)(a + c * 8) = *(const uint4*)h;
    }
}

// ---------------- launch ----------------
extern "C" void kernel_launch(void* const* d_in, const int* in_sizes, int n_in,
                              void* d_out, int out_size) {
    const float* x = (const float*)d_in[0];
    const float* Wq = (const float*)d_in[1];
    const float* bq = (const float*)d_in[2];
    const float* Wk = (const float*)d_in[3];
    const float* bk = (const float*)d_in[4];
    const float* Wv = (const float*)d_in[5];
    const float* bv = (const float*)d_in[6];
    const float* gamma = (const float*)d_in[7];
    float* out = (float*)d_out;

    norm_kernel<<<1, 256>>>(Wq, Wk, Wv);
    qk_proj<<<dim3((NN + 255) / 256, BB), 256>>>(x, Wq, bq, Wk, bk);
    v_gemm<<<dim3((NN + 127) / 128, CC / 128, BB), 256>>>(Wv, x, bv);

    // energy = q k^T / norm -> bf16 att
    tc_gemm<2><<<dim3((NN + 127) / 128, (NN + 127) / 128, BB), 256>>>(
        nullptr, nullptr, nullptr, 0.f);

    softmax_rows<<<BB * NN, 256>>>();

    // out = gamma * (v att^T) / bound + x
    double bound = exp(sqrt(3.0)) * sqrt((double)NN / (double)CC) + 2.0 * sqrt(6.0);
    float inv_bound = (float)(1.0 / bound);
    tc_gemm<1><<<dim3((NN + 127) / 128, CC / 128, BB), 256>>>(out, x, gamma, inv_bound);
}

// round 5
// speedup vs baseline: 3.2701x; 1.1235x over previous
#include <cuda_runtime.h>
#include <cuda_bf16.h>
#include <math.h>
#include <stdint.h>

#define BB 4
#define CC 256
#define CQ 32
#define NN 3136

// flash tiling
#define BM 32                 // query rows per CTA
#define BJ 64                 // keys per stage
#define NST (NN / BJ)         // 49 stages (exact)
#define KP 40                 // K smem pitch (bf16)
#define VP 72                 // V smem pitch (bf16)
#define KSTG (BJ * KP)        // 2560 elems
#define VSTG (CC * VP)        // 18432 elems
#define OBP 257               // O transpose buffer pitch (floats)
#define SMEM_BYTES (2 * KSTG * 2 + 2 * VSTG * 2 + 288 * 4)  // 85120

// ---------------- scratch ----------------
__device__ __nv_bfloat16 g_qh[(size_t)BB * NN * CQ];   // q [B][N][32]
__device__ __nv_bfloat16 g_kh[(size_t)BB * NN * CQ];   // k [B][N][32]
__device__ __nv_bfloat16 g_vh[(size_t)BB * CC * NN];   // v [B][C][N]
__device__ float g_scalars[4];                         // [0] = 1/norm_value

// ---------------- helpers ----------------
__device__ __forceinline__ float warpRedMax(float v) {
#pragma unroll
    for (int o = 16; o > 0; o >>= 1) v = fmaxf(v, __shfl_xor_sync(0xffffffffu, v, o));
    return v;
}
__device__ __forceinline__ float warpRedSum(float v) {
#pragma unroll
    for (int o = 16; o > 0; o >>= 1) v += __shfl_xor_sync(0xffffffffu, v, o);
    return v;
}

__device__ __forceinline__ void mma_bf16(float* d, uint32_t a0, uint32_t a1,
                                         uint32_t a2, uint32_t a3,
                                         uint32_t b0, uint32_t b1) {
    asm volatile(
        "mma.sync.aligned.m16n8k16.row.col.f32.bf16.bf16.f32 "
        "{%0,%1,%2,%3}, {%4,%5,%6,%7}, {%8,%9}, {%0,%1,%2,%3};\n"
        : "+f"(d[0]), "+f"(d[1]), "+f"(d[2]), "+f"(d[3])
        : "r"(a0), "r"(a1), "r"(a2), "r"(a3), "r"(b0), "r"(b1));
}

__device__ __forceinline__ void cp16(uint32_t dst_smem, const void* src) {
    asm volatile("cp.async.cg.shared.global [%0], [%1], 16;\n" ::"r"(dst_smem),
                 "l"(src));
}
#define CP_COMMIT() asm volatile("cp.async.commit_group;\n" ::: "memory")
#define CP_WAIT1() asm volatile("cp.async.wait_group 1;\n" ::: "memory")
#define CP_WAIT0() asm volatile("cp.async.wait_group 0;\n" ::: "memory")

__device__ __forceinline__ uint32_t pack_bf16(float a, float b) {
    __nv_bfloat162 h = __floats2bfloat162_rn(a, b);
    return *(uint32_t*)&h;
}

// ---------------- norm_value ----------------
__global__ void norm_kernel(const float* __restrict__ Wq,
                            const float* __restrict__ Wk,
                            const float* __restrict__ Wv) {
    __shared__ float ssum[8];
    __shared__ float smax[8];
    int tid = threadIdx.x, lane = tid & 31, wid = tid >> 5;

    float s = 0.f;
    for (int i = tid; i < CQ * CC; i += 256) { float w = Wq[i]; s = fmaf(w, w, s); }

    float vk = 0.f;
#pragma unroll
    for (int o = 0; o < CQ; o++) { float w = Wk[o * CC + tid]; vk = fmaf(w, w, vk); }
    float vv = 0.f;
    for (int o = 0; o < CC; o++) { float w = Wv[o * CC + tid]; vv = fmaf(w, w, vv); }
    float m = fmaxf(vk, vv);

    s = warpRedSum(s);
    m = warpRedMax(m);
    if (lane == 0) { ssum[wid] = s; smax[wid] = m; }
    __syncthreads();
    if (tid == 0) {
        float u2 = 0.f, mm = -1e30f;
#pragma unroll
        for (int i = 0; i < 8; i++) { u2 += ssum[i]; mm = fmaxf(mm, smax[i]); }
        g_scalars[0] = 1.0f / (sqrtf(u2) * sqrtf(mm));
    }
}

// ---------------- q,k projection -> bf16 [B][N][32] ----------------
__global__ __launch_bounds__(256) void qk_proj(const float* __restrict__ x,
                                               const float* __restrict__ Wq,
                                               const float* __restrict__ bq,
                                               const float* __restrict__ Wk,
                                               const float* __restrict__ bk) {
    __shared__ float Wqs[CQ][128];
    __shared__ float Wks[CQ][128];
    const int tid = threadIdx.x;
    const int b = blockIdx.y;
    const int n = blockIdx.x * 256 + tid;

    float accq[CQ], acck[CQ];
#pragma unroll
    for (int o = 0; o < CQ; o++) { accq[o] = bq[o]; acck[o] = bk[o]; }

    const float* xb = x + (size_t)b * CC * NN;

    for (int cc = 0; cc < CC; cc += 128) {
        for (int t = tid; t < CQ * 128; t += 256) {
            int o = t >> 7, c = t & 127;
            Wqs[o][c] = Wq[o * CC + cc + c];
            Wks[o][c] = Wk[o * CC + cc + c];
        }
        __syncthreads();
        if (n < NN) {
            for (int ci = 0; ci < 128; ci++) {
                float xv = xb[(size_t)(cc + ci) * NN + n];
#pragma unroll
                for (int o = 0; o < CQ; o++) {
                    accq[o] = fmaf(Wqs[o][ci], xv, accq[o]);
                    acck[o] = fmaf(Wks[o][ci], xv, acck[o]);
                }
            }
        }
        __syncthreads();
    }
    if (n < NN) {
        __nv_bfloat16 hq[CQ], hk[CQ];
#pragma unroll
        for (int o = 0; o < CQ; o++) {
            hq[o] = __float2bfloat16(accq[o]);
            hk[o] = __float2bfloat16(acck[o]);
        }
        uint4* qp = (uint4*)(g_qh + ((size_t)b * NN + n) * CQ);
        uint4* kp = (uint4*)(g_kh + ((size_t)b * NN + n) * CQ);
#pragma unroll
        for (int u = 0; u < 4; u++) {
            qp[u] = ((const uint4*)hq)[u];
            kp[u] = ((const uint4*)hk)[u];
        }
    }
}

// ---------------- v = Wv x + bv -> bf16 [B][C][N] ----------------
__global__ __launch_bounds__(256) void v_gemm(const float* __restrict__ Wv,
                                              const float* __restrict__ x,
                                              const float* __restrict__ bv) {
    __shared__ float As[32][132];
    __shared__ float Bs[32][132];
    const int tid = threadIdx.x;
    const int bz = blockIdx.z;
    const int m0 = blockIdx.y * 128;
    const int n0 = blockIdx.x * 128;

    const float* A = Wv;
    const float* Bm = x + (size_t)bz * CC * NN;
    __nv_bfloat16* C = g_vh + (size_t)bz * CC * NN;

    float acc[8][8];
#pragma unroll
    for (int i = 0; i < 8; i++)
#pragma unroll
        for (int j = 0; j < 8; j++) acc[i][j] = 0.f;

    const int tm = (tid & 15) * 4;
    const int tn = (tid >> 4) * 4;
    const int tr = tid >> 3;
    const int tk4 = tid & 7;
    const int dk = tid >> 5;
    const int dn4 = tid & 31;

    for (int k0 = 0; k0 < CC; k0 += 32) {
#pragma unroll
        for (int p = 0; p < 4; p++) {
            int m = tr + p * 32;
            int row = m0 + m;
            float4 av = make_float4(0.f, 0.f, 0.f, 0.f);
            if (row < CC) av = *(const float4*)(A + (long)row * CC + k0 + tk4 * 4);
            As[tk4 * 4 + 0][m] = av.x;
            As[tk4 * 4 + 1][m] = av.y;
            As[tk4 * 4 + 2][m] = av.z;
            As[tk4 * 4 + 3][m] = av.w;
        }
#pragma unroll
        for (int p = 0; p < 4; p++) {
            int k = dk + p * 8;
            int col = n0 + dn4 * 4;
            float4 bvv = make_float4(0.f, 0.f, 0.f, 0.f);
            if (col < NN) bvv = *(const float4*)(Bm + (long)(k0 + k) * NN + col);
            *(float4*)&Bs[k][dn4 * 4] = bvv;
        }
        __syncthreads();
#pragma unroll
        for (int k = 0; k < 32; k++) {
            float ar[8], br[8];
            *(float4*)&ar[0] = *(const float4*)&As[k][tm];
            *(float4*)&ar[4] = *(const float4*)&As[k][tm + 64];
            *(float4*)&br[0] = *(const float4*)&Bs[k][tn];
            *(float4*)&br[4] = *(const float4*)&Bs[k][tn + 64];
#pragma unroll
            for (int i = 0; i < 8; i++)
#pragma unroll
                for (int j = 0; j < 8; j++) acc[i][j] = fmaf(ar[i], br[j], acc[i][j]);
        }
        __syncthreads();
    }

#pragma unroll
    for (int i = 0; i < 8; i++) {
        int mi = m0 + tm + ((i < 4) ? i : 60 + i);
        if (mi >= CC) continue;
        float bias = bv[mi];
#pragma unroll
        for (int j = 0; j < 8; j++) {
            int nj = n0 + tn + ((j < 4) ? j : 60 + j);
            if (nj >= NN) continue;
            C[(long)mi * NN + nj] = __float2bfloat16(acc[i][j] + bias);
        }
    }
}

// ---------------- fused flash attention + epilogue ----------------
// grid (NN/BM = 98, BB), 256 threads = 8 warps: 2 m-warps x 4 j-warps.
// Each warp: 16 query rows, 16-key slice of each 64-key stage, full C=256 output.
// Online softmax per warp over its disjoint j subset; split-j merge at the end.
__global__ __launch_bounds__(256, 1) void flash_kernel(float* __restrict__ out,
                                                       const float* __restrict__ xr,
                                                       const float* __restrict__ gamma,
                                                       float inv_bound) {
    extern __shared__ char dsm[];
    __nv_bfloat16* Ks = (__nv_bfloat16*)dsm;                       // 2*KSTG
    __nv_bfloat16* Vs = (__nv_bfloat16*)(dsm + 2 * KSTG * 2);      // 2*VSTG
    float* stats = (float*)(dsm + 2 * KSTG * 2 + 2 * VSTG * 2);    // 288 floats
    float* Obuf = (float*)(dsm + 2 * KSTG * 2);                    // reuse V region
    float* m_s = stats;          // [4][32]
    float* l_s = stats + 128;    // [4][32]
    float* inv_s = stats + 256;  // [32]

    const int tid = threadIdx.x;
    const int lane = tid & 31;
    const int wid = tid >> 5;
    const int mw = wid >> 2;   // 0..1
    const int jw = wid & 3;    // 0..3
    const int b = blockIdx.y;
    const int n0 = blockIdx.x * BM;

    const __nv_bfloat16* qg = g_qh + ((size_t)b * NN + n0 + mw * 16) * CQ;
    const __nv_bfloat16* kg = g_kh + (size_t)b * NN * CQ;
    const __nv_bfloat16* vg = g_vh + (size_t)b * CC * NN;

    // ---- Q fragments (held in registers for the whole kernel) ----
    uint32_t aq[2][4];
    {
        int r = lane >> 2;
#pragma unroll
        for (int kc = 0; kc < 2; kc++) {
            int kk = kc * 16 + (lane & 3) * 2;
            aq[kc][0] = *(const uint32_t*)(qg + (size_t)r * CQ + kk);
            aq[kc][1] = *(const uint32_t*)(qg + (size_t)(r + 8) * CQ + kk);
            aq[kc][2] = *(const uint32_t*)(qg + (size_t)r * CQ + kk + 8);
            aq[kc][3] = *(const uint32_t*)(qg + (size_t)(r + 8) * CQ + kk + 8);
        }
    }

    float o[32][4];
#pragma unroll
    for (int i = 0; i < 32; i++) {
        o[i][0] = 0.f; o[i][1] = 0.f; o[i][2] = 0.f; o[i][3] = 0.f;
    }
    float mA = -1e30f, mB = -1e30f, lA = 0.f, lB = 0.f;
    const float sc = g_scalars[0];

    // ---- stage loader (cp.async, 256 threads) ----
    const int krow = tid >> 2, kch = tid & 3;
    const int vrow = tid >> 3, vch = tid & 7;
    auto load_stage = [&](int s, int buf) {
        int j0 = s * BJ;
        cp16((uint32_t)__cvta_generic_to_shared(Ks + buf * KSTG + krow * KP + kch * 8),
             kg + (size_t)(j0 + krow) * CQ + kch * 8);
#pragma unroll
        for (int p = 0; p < 8; p++) {
            int c = vrow + p * 32;
            cp16((uint32_t)__cvta_generic_to_shared(Vs + buf * VSTG + c * VP + vch * 8),
                 vg + (size_t)c * NN + j0 + vch * 8);
        }
    };

    load_stage(0, 0);
    CP_COMMIT();

    for (int s = 0; s < NST; s++) {
        if (s + 1 < NST) {
            load_stage(s + 1, (s + 1) & 1);
            CP_COMMIT();
            CP_WAIT1();
        } else {
            CP_WAIT0();
        }
        __syncthreads();

        const int buf = s & 1;
        const __nv_bfloat16* Kb = Ks + buf * KSTG;
        const __nv_bfloat16* Vb = Vs + buf * VSTG;

        // ---- S = Q K^T on this warp's 16-key slice ----
        float sv[2][4];
#pragma unroll
        for (int nt = 0; nt < 2; nt++) {
            sv[nt][0] = 0.f; sv[nt][1] = 0.f; sv[nt][2] = 0.f; sv[nt][3] = 0.f;
        }
#pragma unroll
        for (int kc = 0; kc < 2; kc++) {
            int kk = kc * 16 + (lane & 3) * 2;
#pragma unroll
            for (int nt = 0; nt < 2; nt++) {
                const __nv_bfloat16* p0 =
                    Kb + (jw * 16 + nt * 8 + (lane >> 2)) * KP + kk;
                mma_bf16(sv[nt], aq[kc][0], aq[kc][1], aq[kc][2], aq[kc][3],
                         *(const uint32_t*)p0, *(const uint32_t*)(p0 + 8));
            }
        }
#pragma unroll
        for (int nt = 0; nt < 2; nt++) {
            sv[nt][0] *= sc; sv[nt][1] *= sc; sv[nt][2] *= sc; sv[nt][3] *= sc;
        }

        // ---- online softmax update (rows A: lane>>2, B: +8) ----
        float tA = fmaxf(fmaxf(sv[0][0], sv[0][1]), fmaxf(sv[1][0], sv[1][1]));
        float tB = fmaxf(fmaxf(sv[0][2], sv[0][3]), fmaxf(sv[1][2], sv[1][3]));
        tA = fmaxf(tA, __shfl_xor_sync(0xffffffffu, tA, 1));
        tA = fmaxf(tA, __shfl_xor_sync(0xffffffffu, tA, 2));
        tB = fmaxf(tB, __shfl_xor_sync(0xffffffffu, tB, 1));
        tB = fmaxf(tB, __shfl_xor_sync(0xffffffffu, tB, 2));
        float mAn = fmaxf(mA, tA), mBn = fmaxf(mB, tB);
        float aAl = __expf(mA - mAn), aBl = __expf(mB - mBn);

        float p00 = __expf(sv[0][0] - mAn), p01 = __expf(sv[0][1] - mAn);
        float p02 = __expf(sv[0][2] - mBn), p03 = __expf(sv[0][3] - mBn);
        float p10 = __expf(sv[1][0] - mAn), p11 = __expf(sv[1][1] - mAn);
        float p12 = __expf(sv[1][2] - mBn), p13 = __expf(sv[1][3] - mBn);

        float sA = p00 + p01 + p10 + p11;
        float sB = p02 + p03 + p12 + p13;
        sA += __shfl_xor_sync(0xffffffffu, sA, 1);
        sA += __shfl_xor_sync(0xffffffffu, sA, 2);
        sB += __shfl_xor_sync(0xffffffffu, sB, 1);
        sB += __shfl_xor_sync(0xffffffffu, sB, 2);
        lA = lA * aAl + sA;
        lB = lB * aBl + sB;
        mA = mAn; mB = mBn;

        uint32_t ap0 = pack_bf16(p00, p01);
        uint32_t ap1 = pack_bf16(p02, p03);
        uint32_t ap2 = pack_bf16(p10, p11);
        uint32_t ap3 = pack_bf16(p12, p13);

        // ---- O = O*alpha + P V (this warp's 16-key slice, all 256 channels) ----
        const __nv_bfloat16* vbase = Vb + jw * 16 + (lane & 3) * 2 + (lane >> 2) * VP;
#pragma unroll
        for (int ct = 0; ct < 32; ct++) {
            o[ct][0] *= aAl; o[ct][1] *= aAl;
            o[ct][2] *= aBl; o[ct][3] *= aBl;
            const __nv_bfloat16* p0 = vbase + ct * 8 * VP;
            mma_bf16(o[ct], ap0, ap1, ap2, ap3,
                     *(const uint32_t*)p0, *(const uint32_t*)(p0 + 8));
        }
        __syncthreads();
    }

    // ---- split-j merge ----
    const int rA = mw * 16 + (lane >> 2);
    const int rB = rA + 8;
    if ((lane & 3) == 0) {
        m_s[jw * 32 + rA] = mA; l_s[jw * 32 + rA] = lA;
        m_s[jw * 32 + rB] = mB; l_s[jw * 32 + rB] = lB;
    }
    __syncthreads();

    float mfA = -1e30f, mfB = -1e30f;
#pragma unroll
    for (int w = 0; w < 4; w++) {
        mfA = fmaxf(mfA, m_s[w * 32 + rA]);
        mfB = fmaxf(mfB, m_s[w * 32 + rB]);
    }
    float lfA = 0.f, lfB = 0.f;
#pragma unroll
    for (int w = 0; w < 4; w++) {
        lfA += l_s[w * 32 + rA] * __expf(m_s[w * 32 + rA] - mfA);
        lfB += l_s[w * 32 + rB] * __expf(m_s[w * 32 + rB] - mfB);
    }
    float selfA = __expf(mA - mfA);
    float selfB = __expf(mB - mfB);
    if (jw == 0 && (lane & 3) == 0) {
        inv_s[rA] = 1.0f / lfA;
        inv_s[rB] = 1.0f / lfB;
    }
    __syncthreads();  // stage loop done; V region reusable as Obuf

    // accumulate alpha-scaled O into Obuf[row][c], serialized over j-warps
#pragma unroll
    for (int w = 0; w < 4; w++) {
        if (jw == w) {
#pragma unroll
            for (int ct = 0; ct < 32; ct++) {
                int c = ct * 8 + 2 * (lane & 3);
                float* pA = Obuf + rA * OBP + c;
                float* pB = Obuf + rB * OBP + c;
                if (w == 0) {
                    pA[0] = selfA * o[ct][0]; pA[1] = selfA * o[ct][1];
                    pB[0] = selfB * o[ct][2]; pB[1] = selfB * o[ct][3];
                } else {
                    pA[0] += selfA * o[ct][0]; pA[1] += selfA * o[ct][1];
                    pB[0] += selfB * o[ct][2]; pB[1] += selfB * o[ct][3];
                }
            }
        }
        __syncthreads();
    }

    // ---- transposed residual epilogue: out[c][n0+i] ----
    const float gscale = gamma[0] * inv_bound;
    const float* xb = xr + (size_t)b * CC * NN;
    float* ob = out + (size_t)b * CC * NN;
    const int i = lane;
    const int crow = tid >> 5;  // 8 channel rows per pass
    for (int cb = 0; cb < CC; cb += 8) {
        int c = cb + crow;
        float val = Obuf[i * OBP + c] * inv_s[i];
        size_t off = (size_t)c * NN + n0 + i;
        ob[off] = fmaf(gscale, val, xb[off]);
    }
}

// ---------------- launch ----------------
extern "C" void kernel_launch(void* const* d_in, const int* in_sizes, int n_in,
                              void* d_out, int out_size) {
    const float* x = (const float*)d_in[0];
    const float* Wq = (const float*)d_in[1];
    const float* bq = (const float*)d_in[2];
    const float* Wk = (const float*)d_in[3];
    const float* bk = (const float*)d_in[4];
    const float* Wv = (const float*)d_in[5];
    const float* bv = (const float*)d_in[6];
    const float* gamma = (const float*)d_in[7];
    float* out = (float*)d_out;

    cudaFuncSetAttribute(flash_kernel, cudaFuncAttributeMaxDynamicSharedMemorySize,
                         SMEM_BYTES);

    norm_kernel<<<1, 256>>>(Wq, Wk, Wv);
    qk_proj<<<dim3((NN + 255) / 256, BB), 256>>>(x, Wq, bq, Wk, bk);
    v_gemm<<<dim3((NN + 127) / 128, CC / 128, BB), 256>>>(Wv, x, bv);

    double bound = exp(sqrt(3.0)) * sqrt((double)NN / (double)CC) + 2.0 * sqrt(6.0);
    float inv_bound = (float)(1.0 / bound);
    flash_kernel<<<dim3(NN / BM, BB), 256, SMEM_BYTES>>>(out, x, gamma, inv_bound);
}

// round 6
// speedup vs baseline: 5.3185x; 1.6264x over previous
#include <cuda_runtime.h>
#include <cuda_bf16.h>
#include <math.h>
#include <stdint.h>

#define BB 4
#define CC 256
#define CQ 32
#define NN 3136
#define MP 320                // packed projection rows: 32 q + 32 k + 256 v

// flash tiling
#define BM 32                 // query rows per CTA
#define BJ 64                 // keys per stage
#define NST (NN / BJ)         // 49 stages (exact)
#define KP 40                 // K smem pitch (bf16)
#define VP 72                 // V smem pitch (bf16)
#define KSTG (BJ * KP)        // 2560 elems
#define VSTG (CC * VP)        // 18432 elems
#define OBP 257               // O transpose buffer pitch (floats)
#define SMEM_BYTES (2 * KSTG * 2 + 2 * VSTG * 2 + 288 * 4)  // 85120

// ---------------- scratch ----------------
__device__ __nv_bfloat16 g_qh[(size_t)BB * NN * CQ];   // q [B][N][32]
__device__ __nv_bfloat16 g_kh[(size_t)BB * NN * CQ];   // k [B][N][32]
__device__ __nv_bfloat16 g_vh[(size_t)BB * CC * NN];   // v [B][C][N]
__device__ __nv_bfloat16 g_xt[(size_t)BB * NN * CC];   // x^T bf16 [B][N][C]
__device__ __nv_bfloat16 g_wh[(size_t)MP * CC];        // [Wq;Wk;Wv] bf16 [320][256]
__device__ float g_scalars[4];                         // [0] = 1/norm_value

// ---------------- helpers ----------------
__device__ __forceinline__ float warpRedMax(float v) {
#pragma unroll
    for (int o = 16; o > 0; o >>= 1) v = fmaxf(v, __shfl_xor_sync(0xffffffffu, v, o));
    return v;
}
__device__ __forceinline__ float warpRedSum(float v) {
#pragma unroll
    for (int o = 16; o > 0; o >>= 1) v += __shfl_xor_sync(0xffffffffu, v, o);
    return v;
}

__device__ __forceinline__ void mma_bf16(float* d, uint32_t a0, uint32_t a1,
                                         uint32_t a2, uint32_t a3,
                                         uint32_t b0, uint32_t b1) {
    asm volatile(
        "mma.sync.aligned.m16n8k16.row.col.f32.bf16.bf16.f32 "
        "{%0,%1,%2,%3}, {%4,%5,%6,%7}, {%8,%9}, {%0,%1,%2,%3};\n"
        : "+f"(d[0]), "+f"(d[1]), "+f"(d[2]), "+f"(d[3])
        : "r"(a0), "r"(a1), "r"(a2), "r"(a3), "r"(b0), "r"(b1));
}

__device__ __forceinline__ void cp16(uint32_t dst_smem, const void* src) {
    asm volatile("cp.async.cg.shared.global [%0], [%1], 16;\n" ::"r"(dst_smem),
                 "l"(src));
}
#define CP_COMMIT() asm volatile("cp.async.commit_group;\n" ::: "memory")
#define CP_WAIT1() asm volatile("cp.async.wait_group 1;\n" ::: "memory")
#define CP_WAIT0() asm volatile("cp.async.wait_group 0;\n" ::: "memory")

__device__ __forceinline__ uint32_t pack_bf16(float a, float b) {
    __nv_bfloat162 h = __floats2bfloat162_rn(a, b);
    return *(uint32_t*)&h;
}

// ---------------- norm_value ----------------
__global__ void norm_kernel(const float* __restrict__ Wq,
                            const float* __restrict__ Wk,
                            const float* __restrict__ Wv) {
    __shared__ float ssum[8];
    __shared__ float smax[8];
    int tid = threadIdx.x, lane = tid & 31, wid = tid >> 5;

    float s = 0.f;
    for (int i = tid; i < CQ * CC; i += 256) { float w = Wq[i]; s = fmaf(w, w, s); }

    float vk = 0.f;
#pragma unroll
    for (int o = 0; o < CQ; o++) { float w = Wk[o * CC + tid]; vk = fmaf(w, w, vk); }
    float vv = 0.f;
    for (int o = 0; o < CC; o++) { float w = Wv[o * CC + tid]; vv = fmaf(w, w, vv); }
    float m = fmaxf(vk, vv);

    s = warpRedSum(s);
    m = warpRedMax(m);
    if (lane == 0) { ssum[wid] = s; smax[wid] = m; }
    __syncthreads();
    if (tid == 0) {
        float u2 = 0.f, mm = -1e30f;
#pragma unroll
        for (int i = 0; i < 8; i++) { u2 += ssum[i]; mm = fmaxf(mm, smax[i]); }
        g_scalars[0] = 1.0f / (sqrtf(u2) * sqrtf(mm));
    }
}

// ---------------- pack weights -> bf16 [320][256] ----------------
__global__ void prep_w(const float* __restrict__ Wq, const float* __restrict__ Wk,
                       const float* __restrict__ Wv) {
    int row = blockIdx.x;
    int c = threadIdx.x;
    float w;
    if (row < 32) w = Wq[row * CC + c];
    else if (row < 64) w = Wk[(row - 32) * CC + c];
    else w = Wv[(row - 64) * CC + c];
    g_wh[row * CC + c] = __float2bfloat16(w);
}

// ---------------- transpose + convert x -> bf16 [B][N][C] ----------------
__global__ __launch_bounds__(256) void xpose(const float* __restrict__ x) {
    __shared__ float t[32][33];
    const int b = blockIdx.z;
    const int n0 = blockIdx.x * 32;
    const int c0 = blockIdx.y * 32;
    const int tx = threadIdx.x & 31;
    const int ty = threadIdx.x >> 5;  // 0..7

    const float* xb = x + (size_t)b * CC * NN;
#pragma unroll
    for (int p = 0; p < 4; p++) {
        int cl = ty + p * 8;
        t[cl][tx] = xb[(size_t)(c0 + cl) * NN + n0 + tx];
    }
    __syncthreads();
    __nv_bfloat16* xt = g_xt + (size_t)b * NN * CC;
#pragma unroll
    for (int p = 0; p < 4; p++) {
        int r = ty + p * 8;  // local n
        xt[(size_t)(n0 + r) * CC + c0 + tx] = __float2bfloat16(t[tx][r]);
    }
}

// ---------------- fused projection GEMM (tensor cores) ----------------
// C[m][n] = sum_k Wpacked[m][k] * xT[n][k] + bias[m], m in [0,320)
// rows 0..31 -> g_qh transposed, 32..63 -> g_kh transposed, 64..319 -> g_vh [C][N]
__global__ __launch_bounds__(256) void proj_mma(const float* __restrict__ bq,
                                                const float* __restrict__ bk,
                                                const float* __restrict__ bv) {
    constexpr int KT = 64;
    constexpr int PITCH = KT + 8;
    __shared__ __nv_bfloat16 As[128 * PITCH];
    __shared__ __nv_bfloat16 Bs[128 * PITCH];

    const int tid = threadIdx.x;
    const int lane = tid & 31;
    const int wid = tid >> 5;
    const int wm = (wid >> 2) * 64;
    const int wn = (wid & 3) * 32;
    const int bz = blockIdx.z;
    const int m0 = blockIdx.y * 128;
    const int n0 = blockIdx.x * 128;

    const __nv_bfloat16* B = g_xt + (size_t)bz * NN * CC;

    float acc[4][4][4];
#pragma unroll
    for (int a = 0; a < 4; a++)
#pragma unroll
        for (int b2 = 0; b2 < 4; b2++)
#pragma unroll
            for (int c = 0; c < 4; c++) acc[a][b2][c] = 0.f;

    const int lk = (tid & 7) * 8;
    const int lrow = tid >> 3;  // 0..31

    for (int k0 = 0; k0 < CC; k0 += KT) {
#pragma unroll
        for (int p = 0; p < 4; p++) {
            int r = lrow + p * 32;
            int grow = m0 + r;
            uint4 v = make_uint4(0u, 0u, 0u, 0u);
            if (grow < MP) v = *(const uint4*)(g_wh + (size_t)grow * CC + k0 + lk);
            *(uint4*)&As[r * PITCH + lk] = v;
        }
#pragma unroll
        for (int p = 0; p < 4; p++) {
            int r = lrow + p * 32;
            int grow = n0 + r;
            uint4 v = make_uint4(0u, 0u, 0u, 0u);
            if (grow < NN) v = *(const uint4*)(B + (size_t)grow * CC + k0 + lk);
            *(uint4*)&Bs[r * PITCH + lk] = v;
        }
        __syncthreads();

#pragma unroll
        for (int kk = 0; kk < KT / 16; kk++) {
            const int kb = kk * 16;
            uint32_t af[4][4], bf[4][2];
#pragma unroll
            for (int mi = 0; mi < 4; mi++) {
                const __nv_bfloat16* p0 =
                    &As[(wm + mi * 16 + (lane >> 2)) * PITCH + kb + (lane & 3) * 2];
                af[mi][0] = *(const uint32_t*)p0;
                af[mi][1] = *(const uint32_t*)(p0 + 8 * PITCH);
                af[mi][2] = *(const uint32_t*)(p0 + 8);
                af[mi][3] = *(const uint32_t*)(p0 + 8 * PITCH + 8);
            }
#pragma unroll
            for (int ni = 0; ni < 4; ni++) {
                const __nv_bfloat16* p0 =
                    &Bs[(wn + ni * 8 + (lane >> 2)) * PITCH + kb + (lane & 3) * 2];
                bf[ni][0] = *(const uint32_t*)p0;
                bf[ni][1] = *(const uint32_t*)(p0 + 8);
            }
#pragma unroll
            for (int mi = 0; mi < 4; mi++)
#pragma unroll
                for (int ni = 0; ni < 4; ni++)
                    mma_bf16(acc[mi][ni], af[mi][0], af[mi][1], af[mi][2], af[mi][3],
                             bf[ni][0], bf[ni][1]);
        }
        __syncthreads();
    }

    // epilogue: bias + scatter
    auto store_row = [&](int row, int col, float v0, float v1) {
        if (row >= MP || col >= NN) return;
        float bias = (row < 32) ? bq[row] : (row < 64) ? bk[row - 32] : bv[row - 64];
        v0 += bias; v1 += bias;
        if (row < 32) {
            __nv_bfloat16* q = g_qh + (size_t)bz * NN * CQ;
            q[(size_t)col * CQ + row] = __float2bfloat16(v0);
            q[(size_t)(col + 1) * CQ + row] = __float2bfloat16(v1);
        } else if (row < 64) {
            __nv_bfloat16* k = g_kh + (size_t)bz * NN * CQ;
            k[(size_t)col * CQ + row - 32] = __float2bfloat16(v0);
            k[(size_t)(col + 1) * CQ + row - 32] = __float2bfloat16(v1);
        } else {
            __nv_bfloat16* v = g_vh + (size_t)bz * CC * NN;
            *(__nv_bfloat162*)(v + (size_t)(row - 64) * NN + col) =
                __floats2bfloat162_rn(v0, v1);
        }
    };

#pragma unroll
    for (int mi = 0; mi < 4; mi++)
#pragma unroll
        for (int ni = 0; ni < 4; ni++) {
            int row = m0 + wm + mi * 16 + (lane >> 2);
            int col = n0 + wn + ni * 8 + (lane & 3) * 2;
            store_row(row, col, acc[mi][ni][0], acc[mi][ni][1]);
            store_row(row + 8, col, acc[mi][ni][2], acc[mi][ni][3]);
        }
}

// ---------------- fused flash attention + epilogue (unchanged from R5) ----------------
__global__ __launch_bounds__(256, 1) void flash_kernel(float* __restrict__ out,
                                                       const float* __restrict__ xr,
                                                       const float* __restrict__ gamma,
                                                       float inv_bound) {
    extern __shared__ char dsm[];
    __nv_bfloat16* Ks = (__nv_bfloat16*)dsm;
    __nv_bfloat16* Vs = (__nv_bfloat16*)(dsm + 2 * KSTG * 2);
    float* stats = (float*)(dsm + 2 * KSTG * 2 + 2 * VSTG * 2);
    float* Obuf = (float*)(dsm + 2 * KSTG * 2);
    float* m_s = stats;
    float* l_s = stats + 128;
    float* inv_s = stats + 256;

    const int tid = threadIdx.x;
    const int lane = tid & 31;
    const int wid = tid >> 5;
    const int mw = wid >> 2;
    const int jw = wid & 3;
    const int b = blockIdx.y;
    const int n0 = blockIdx.x * BM;

    const __nv_bfloat16* qg = g_qh + ((size_t)b * NN + n0 + mw * 16) * CQ;
    const __nv_bfloat16* kg = g_kh + (size_t)b * NN * CQ;
    const __nv_bfloat16* vg = g_vh + (size_t)b * CC * NN;

    uint32_t aq[2][4];
    {
        int r = lane >> 2;
#pragma unroll
        for (int kc = 0; kc < 2; kc++) {
            int kk = kc * 16 + (lane & 3) * 2;
            aq[kc][0] = *(const uint32_t*)(qg + (size_t)r * CQ + kk);
            aq[kc][1] = *(const uint32_t*)(qg + (size_t)(r + 8) * CQ + kk);
            aq[kc][2] = *(const uint32_t*)(qg + (size_t)r * CQ + kk + 8);
            aq[kc][3] = *(const uint32_t*)(qg + (size_t)(r + 8) * CQ + kk + 8);
        }
    }

    float o[32][4];
#pragma unroll
    for (int i = 0; i < 32; i++) {
        o[i][0] = 0.f; o[i][1] = 0.f; o[i][2] = 0.f; o[i][3] = 0.f;
    }
    float mA = -1e30f, mB = -1e30f, lA = 0.f, lB = 0.f;
    const float sc = g_scalars[0];

    const int krow = tid >> 2, kch = tid & 3;
    const int vrow = tid >> 3, vch = tid & 7;
    auto load_stage = [&](int s, int buf) {
        int j0 = s * BJ;
        cp16((uint32_t)__cvta_generic_to_shared(Ks + buf * KSTG + krow * KP + kch * 8),
             kg + (size_t)(j0 + krow) * CQ + kch * 8);
#pragma unroll
        for (int p = 0; p < 8; p++) {
            int c = vrow + p * 32;
            cp16((uint32_t)__cvta_generic_to_shared(Vs + buf * VSTG + c * VP + vch * 8),
                 vg + (size_t)c * NN + j0 + vch * 8);
        }
    };

    load_stage(0, 0);
    CP_COMMIT();

    for (int s = 0; s < NST; s++) {
        if (s + 1 < NST) {
            load_stage(s + 1, (s + 1) & 1);
            CP_COMMIT();
            CP_WAIT1();
        } else {
            CP_WAIT0();
        }
        __syncthreads();

        const int buf = s & 1;
        const __nv_bfloat16* Kb = Ks + buf * KSTG;
        const __nv_bfloat16* Vb = Vs + buf * VSTG;

        float sv[2][4];
#pragma unroll
        for (int nt = 0; nt < 2; nt++) {
            sv[nt][0] = 0.f; sv[nt][1] = 0.f; sv[nt][2] = 0.f; sv[nt][3] = 0.f;
        }
#pragma unroll
        for (int kc = 0; kc < 2; kc++) {
            int kk = kc * 16 + (lane & 3) * 2;
#pragma unroll
            for (int nt = 0; nt < 2; nt++) {
                const __nv_bfloat16* p0 =
                    Kb + (jw * 16 + nt * 8 + (lane >> 2)) * KP + kk;
                mma_bf16(sv[nt], aq[kc][0], aq[kc][1], aq[kc][2], aq[kc][3],
                         *(const uint32_t*)p0, *(const uint32_t*)(p0 + 8));
            }
        }
#pragma unroll
        for (int nt = 0; nt < 2; nt++) {
            sv[nt][0] *= sc; sv[nt][1] *= sc; sv[nt][2] *= sc; sv[nt][3] *= sc;
        }

        float tA = fmaxf(fmaxf(sv[0][0], sv[0][1]), fmaxf(sv[1][0], sv[1][1]));
        float tB = fmaxf(fmaxf(sv[0][2], sv[0][3]), fmaxf(sv[1][2], sv[1][3]));
        tA = fmaxf(tA, __shfl_xor_sync(0xffffffffu, tA, 1));
        tA = fmaxf(tA, __shfl_xor_sync(0xffffffffu, tA, 2));
        tB = fmaxf(tB, __shfl_xor_sync(0xffffffffu, tB, 1));
        tB = fmaxf(tB, __shfl_xor_sync(0xffffffffu, tB, 2));
        float mAn = fmaxf(mA, tA), mBn = fmaxf(mB, tB);
        float aAl = __expf(mA - mAn), aBl = __expf(mB - mBn);

        float p00 = __expf(sv[0][0] - mAn), p01 = __expf(sv[0][1] - mAn);
        float p02 = __expf(sv[0][2] - mBn), p03 = __expf(sv[0][3] - mBn);
        float p10 = __expf(sv[1][0] - mAn), p11 = __expf(sv[1][1] - mAn);
        float p12 = __expf(sv[1][2] - mBn), p13 = __expf(sv[1][3] - mBn);

        float sA = p00 + p01 + p10 + p11;
        float sB = p02 + p03 + p12 + p13;
        sA += __shfl_xor_sync(0xffffffffu, sA, 1);
        sA += __shfl_xor_sync(0xffffffffu, sA, 2);
        sB += __shfl_xor_sync(0xffffffffu, sB, 1);
        sB += __shfl_xor_sync(0xffffffffu, sB, 2);
        lA = lA * aAl + sA;
        lB = lB * aBl + sB;
        mA = mAn; mB = mBn;

        uint32_t ap0 = pack_bf16(p00, p01);
        uint32_t ap1 = pack_bf16(p02, p03);
        uint32_t ap2 = pack_bf16(p10, p11);
        uint32_t ap3 = pack_bf16(p12, p13);

        const __nv_bfloat16* vbase = Vb + jw * 16 + (lane & 3) * 2 + (lane >> 2) * VP;
#pragma unroll
        for (int ct = 0; ct < 32; ct++) {
            o[ct][0] *= aAl; o[ct][1] *= aAl;
            o[ct][2] *= aBl; o[ct][3] *= aBl;
            const __nv_bfloat16* p0 = vbase + ct * 8 * VP;
            mma_bf16(o[ct], ap0, ap1, ap2, ap3,
                     *(const uint32_t*)p0, *(const uint32_t*)(p0 + 8));
        }
        __syncthreads();
    }

    const int rA = mw * 16 + (lane >> 2);
    const int rB = rA + 8;
    if ((lane & 3) == 0) {
        m_s[jw * 32 + rA] = mA; l_s[jw * 32 + rA] = lA;
        m_s[jw * 32 + rB] = mB; l_s[jw * 32 + rB] = lB;
    }
    __syncthreads();

    float mfA = -1e30f, mfB = -1e30f;
#pragma unroll
    for (int w = 0; w < 4; w++) {
        mfA = fmaxf(mfA, m_s[w * 32 + rA]);
        mfB = fmaxf(mfB, m_s[w * 32 + rB]);
    }
    float lfA = 0.f, lfB = 0.f;
#pragma unroll
    for (int w = 0; w < 4; w++) {
        lfA += l_s[w * 32 + rA] * __expf(m_s[w * 32 + rA] - mfA);
        lfB += l_s[w * 32 + rB] * __expf(m_s[w * 32 + rB] - mfB);
    }
    float selfA = __expf(mA - mfA);
    float selfB = __expf(mB - mfB);
    if (jw == 0 && (lane & 3) == 0) {
        inv_s[rA] = 1.0f / lfA;
        inv_s[rB] = 1.0f / lfB;
    }
    __syncthreads();

#pragma unroll
    for (int w = 0; w < 4; w++) {
        if (jw == w) {
#pragma unroll
            for (int ct = 0; ct < 32; ct++) {
                int c = ct * 8 + 2 * (lane & 3);
                float* pA = Obuf + rA * OBP + c;
                float* pB = Obuf + rB * OBP + c;
                if (w == 0) {
                    pA[0] = selfA * o[ct][0]; pA[1] = selfA * o[ct][1];
                    pB[0] = selfB * o[ct][2]; pB[1] = selfB * o[ct][3];
                } else {
                    pA[0] += selfA * o[ct][0]; pA[1] += selfA * o[ct][1];
                    pB[0] += selfB * o[ct][2]; pB[1] += selfB * o[ct][3];
                }
            }
        }
        __syncthreads();
    }

    const float gscale = gamma[0] * inv_bound;
    const float* xb = xr + (size_t)b * CC * NN;
    float* ob = out + (size_t)b * CC * NN;
    const int i = lane;
    const int crow = tid >> 5;
    for (int cb = 0; cb < CC; cb += 8) {
        int c = cb + crow;
        float val = Obuf[i * OBP + c] * inv_s[i];
        size_t off = (size_t)c * NN + n0 + i;
        ob[off] = fmaf(gscale, val, xb[off]);
    }
}

// ---------------- launch ----------------
extern "C" void kernel_launch(void* const* d_in, const int* in_sizes, int n_in,
                              void* d_out, int out_size) {
    const float* x = (const float*)d_in[0];
    const float* Wq = (const float*)d_in[1];
    const float* bq = (const float*)d_in[2];
    const float* Wk = (const float*)d_in[3];
    const float* bk = (const float*)d_in[4];
    const float* Wv = (const float*)d_in[5];
    const float* bv = (const float*)d_in[6];
    const float* gamma = (const float*)d_in[7];
    float* out = (float*)d_out;

    cudaFuncSetAttribute(flash_kernel, cudaFuncAttributeMaxDynamicSharedMemorySize,
                         SMEM_BYTES);

    norm_kernel<<<1, 256>>>(Wq, Wk, Wv);
    prep_w<<<MP, CC>>>(Wq, Wk, Wv);
    xpose<<<dim3(NN / 32, CC / 32, BB), 256>>>(x);
    proj_mma<<<dim3((NN + 127) / 128, (MP + 127) / 128, BB), 256>>>(bq, bk, bv);

    double bound = exp(sqrt(3.0)) * sqrt((double)NN / (double)CC) + 2.0 * sqrt(6.0);
    float inv_bound = (float)(1.0 / bound);
    flash_kernel<<<dim3(NN / BM, BB), 256, SMEM_BYTES>>>(out, x, gamma, inv_bound);
}